// round 2
// baseline (speedup 1.0000x reference)
#include <cuda_runtime.h>

// Problem constants
#define NB   8192      // batch (rows/cols of logits)
#define DK   512       // embedding dim
#define NCAP 256       // max same-label entries stored per row (~82 avg with 100 classes)

// GEMM tiling
#define BM 128
#define BN 128
#define BK 32
#define SMS 132        // smem row stride (floats)

__device__ float g_S[NB];            // sum of exp(L - SHIFT) over different-label cols, per row
__device__ int   g_cnt[NB];          // same-label (i!=j) count per row
__device__ float g_scr[NB * NCAP];   // stored same-label scaled logits
__device__ float g_rowloss[NB];      // per-row ce/count

#define INV_T 14.285714285714285f    // 1/0.07 ; also the shift (max logit since |e|=1)

__global__ void init_kernel() {
    int i = blockIdx.x * blockDim.x + threadIdx.x;
    if (i < NB) { g_S[i] = 0.f; g_cnt[i] = 0; }
}

// Fused GEMM (E @ E^T) + epilogue: accumulate exp-sums for different-label pairs,
// scatter same-label logits to scratch. One 128x128 output tile per block.
__global__ __launch_bounds__(256) void gemm_kernel(const float* __restrict__ E,
                                                   const int* __restrict__ lab) {
    __shared__ float As[BK][SMS];
    __shared__ float Bs[BK][SMS];
    __shared__ int sLI[BM], sLJ[BN];

    const int t  = threadIdx.x;
    const int tx = t & 15;        // 16 threads across cols
    const int ty = t >> 4;        // 16 threads across rows
    const int i0 = blockIdx.y * BM;
    const int j0 = blockIdx.x * BN;

    if (t < BM)            sLI[t]        = lab[i0 + t];
    else if (t < BM + BN)  sLJ[t - BM]   = lab[j0 + (t - BM)];

    float acc[8][8];
#pragma unroll
    for (int a = 0; a < 8; a++)
#pragma unroll
        for (int b = 0; b < 8; b++) acc[a][b] = 0.f;

    for (int k0 = 0; k0 < DK; k0 += BK) {
        __syncthreads();
        // Load 128x32 A-tile and B-tile (transposed into [k][row]) with float4 loads
#pragma unroll
        for (int i = 0; i < 4; i++) {
            int v   = t + i * 256;
            int row = v >> 3;           // 0..127
            int q   = v & 7;            // float4 index within 32-wide k chunk
            float4 ga = *(const float4*)&E[(i0 + row) * DK + k0 + q * 4];
            As[q * 4 + 0][row] = ga.x; As[q * 4 + 1][row] = ga.y;
            As[q * 4 + 2][row] = ga.z; As[q * 4 + 3][row] = ga.w;
            float4 gb = *(const float4*)&E[(j0 + row) * DK + k0 + q * 4];
            Bs[q * 4 + 0][row] = gb.x; Bs[q * 4 + 1][row] = gb.y;
            Bs[q * 4 + 2][row] = gb.z; Bs[q * 4 + 3][row] = gb.w;
        }
        __syncthreads();
#pragma unroll
        for (int k = 0; k < BK; k++) {
            float4 a0 = *(float4*)&As[k][ty * 8];
            float4 a1 = *(float4*)&As[k][ty * 8 + 4];
            float4 b0 = *(float4*)&Bs[k][tx * 8];
            float4 b1 = *(float4*)&Bs[k][tx * 8 + 4];
            float av[8] = {a0.x, a0.y, a0.z, a0.w, a1.x, a1.y, a1.z, a1.w};
            float bv[8] = {b0.x, b0.y, b0.z, b0.w, b1.x, b1.y, b1.z, b1.w};
#pragma unroll
            for (int a = 0; a < 8; a++)
#pragma unroll
                for (int b = 0; b < 8; b++)
                    acc[a][b] += av[a] * bv[b];
        }
    }

    // Epilogue: diff-label -> add exp(L-SHIFT) to row-sum; same-label off-diag -> scatter.
#pragma unroll
    for (int rr = 0; rr < 8; rr++) {
        int irow = ty * 8 + rr;
        int gi   = i0 + irow;
        int li   = sLI[irow];
        float rs = 0.f;
#pragma unroll
        for (int cc = 0; cc < 8; cc++) {
            int jcol = tx * 8 + cc;
            int gj   = j0 + jcol;
            float L  = acc[rr][cc] * INV_T;
            if (li != sLJ[jcol]) {
                rs += __expf(L - INV_T);
            } else if (gi != gj) {
                int p = atomicAdd(&g_cnt[gi], 1);
                if (p < NCAP) g_scr[gi * NCAP + p] = L;
            }
        }
        // Reduce over the 16 lanes sharing this row (contiguous half-warp)
        rs += __shfl_xor_sync(0xffffffffu, rs, 8);
        rs += __shfl_xor_sync(0xffffffffu, rs, 4);
        rs += __shfl_xor_sync(0xffffffffu, rs, 2);
        rs += __shfl_xor_sync(0xffffffffu, rs, 1);
        if (tx == 0) atomicAdd(&g_S[gi], rs);
    }
}

// Pass 2: per-row ce sum / count.  base[i] = log(S_i) + SHIFT.
__global__ void row_loss_kernel() {
    int i = blockIdx.x * blockDim.x + threadIdx.x;
    if (i >= NB) return;
    int c = g_cnt[i];
    float out = 0.f;
    if (c > 0) {
        float base = logf(g_S[i]) + INV_T;
        float s = 0.f;
        int cap = c < NCAP ? c : NCAP;
        for (int p = 0; p < cap; p++) {
            float L = g_scr[i * NCAP + p];
            s += log1pf(__expf(base - L));   // base-L bounded, no overflow
        }
        out = s / (float)c;
    }
    g_rowloss[i] = out;
}

// Deterministic final reduction (single block).
__global__ void reduce_kernel(float* __restrict__ out) {
    __shared__ float sm[256];
    float s = 0.f;
    for (int i = threadIdx.x; i < NB; i += 256) s += g_rowloss[i];
    sm[threadIdx.x] = s;
    __syncthreads();
    for (int o = 128; o > 0; o >>= 1) {
        if (threadIdx.x < o) sm[threadIdx.x] += sm[threadIdx.x + o];
        __syncthreads();
    }
    if (threadIdx.x == 0) out[0] = sm[0] * (1.0f / (float)NB);
}

extern "C" void kernel_launch(void* const* d_in, const int* in_sizes, int n_in,
                              void* d_out, int out_size) {
    const float* E   = (const float*)d_in[0];
    const int*   lab = (const int*)d_in[1];
    float*       out = (float*)d_out;

    init_kernel<<<NB / 256, 256>>>();
    dim3 grid(NB / BN, NB / BM);   // 64 x 64 tiles
    gemm_kernel<<<grid, 256>>>(E, lab);
    row_loss_kernel<<<NB / 256, 256>>>();
    reduce_kernel<<<1, 256>>>(out);
}

// round 4
// speedup vs baseline: 3.6854x; 3.6854x over previous
#include <cuda_runtime.h>
#include <cuda_bf16.h>
#include <cstdint>
#include <math.h>

#define NB   8192
#define DK   512
#define NCAP 256
#define INV_T 14.285714285714285f

// ---------------- device scratch ----------------
__device__ float g_S[NB];
__device__ int   g_cnt[NB];
__device__ float g_scr[NB * NCAP];
__device__ float g_rowloss[NB];
__device__ __nv_bfloat16 g_hi[NB * DK];
__device__ __nv_bfloat16 g_lo[NB * DK];

// ---------------- tile geometry ----------------
#define TSTR   40                     // halves per smem row (80B: conflict-free ldmatrix)
#define TILE_B (128 * TSTR * 2)       // 10240 bytes per 128x32 bf16 tile
#define SM_LAB (8 * TILE_B)           // after 2 stages x 4 tiles
#define SM_TOTAL (SM_LAB + 1024)

// ---------------- helpers ----------------
__device__ __forceinline__ uint32_t smem_u32(const void* p) {
    uint32_t a;
    asm("{ .reg .u64 t; cvta.to.shared.u64 t, %1; cvt.u32.u64 %0, t; }" : "=r"(a) : "l"(p));
    return a;
}
__device__ __forceinline__ void cp16(uint32_t dst, const void* src) {
    asm volatile("cp.async.cg.shared.global [%0], [%1], 16;" :: "r"(dst), "l"(src));
}
__device__ __forceinline__ void cp_commit() { asm volatile("cp.async.commit_group;"); }
template<int N> __device__ __forceinline__ void cp_wait() {
    asm volatile("cp.async.wait_group %0;" :: "n"(N));
}
__device__ __forceinline__ void ldsm4(uint32_t& r0, uint32_t& r1, uint32_t& r2, uint32_t& r3,
                                      uint32_t addr) {
    asm volatile("ldmatrix.sync.aligned.m8n8.x4.shared.b16 {%0,%1,%2,%3}, [%4];"
                 : "=r"(r0), "=r"(r1), "=r"(r2), "=r"(r3) : "r"(addr));
}
__device__ __forceinline__ void mma16816(float* c, const uint32_t* a, const uint32_t* b) {
    asm volatile("mma.sync.aligned.m16n8k16.row.col.f32.bf16.bf16.f32 "
                 "{%0,%1,%2,%3},{%4,%5,%6,%7},{%8,%9},{%0,%1,%2,%3};"
                 : "+f"(c[0]), "+f"(c[1]), "+f"(c[2]), "+f"(c[3])
                 : "r"(a[0]), "r"(a[1]), "r"(a[2]), "r"(a[3]), "r"(b[0]), "r"(b[1]));
}

__global__ void init_kernel() {
    int i = blockIdx.x * blockDim.x + threadIdx.x;
    if (i < NB) { g_S[i] = 0.f; g_cnt[i] = 0; }
}

__global__ void convert_kernel(const float* __restrict__ E) {
    int i = blockIdx.x * blockDim.x + threadIdx.x;
    float x = E[i];
    __nv_bfloat16 h = __float2bfloat16(x);
    g_hi[i] = h;
    g_lo[i] = __float2bfloat16(x - __bfloat162float(h));
}

extern __shared__ char smem[];

// Upper-triangle tiled symmetric GEMM (E E^T) on HMMA, fused SINCERE epilogue.
__global__ void __launch_bounds__(256, 2) gemm_mma(const int* __restrict__ lab) {
    const int t   = threadIdx.x;
    const int lid = t & 31;
    const int wid = t >> 5;
    const int warp_m = wid & 3;     // 4 warps down  (32 rows each)
    const int warp_n = wid >> 2;    // 2 warps across (64 cols each)

    // decode upper-triangle tile (ti <= tj), cum(t) = t*(129-t)/2
    int b  = blockIdx.x;
    int ti = (int)((129.0 - sqrt(129.0 * 129.0 - 8.0 * (double)b)) * 0.5);
    while (ti * (129 - ti) / 2 > b) ti--;
    while ((ti + 1) * (128 - ti) / 2 <= b) ti++;
    const int tj = ti + (b - ti * (129 - ti) / 2);
    const int i0 = ti * 128, j0 = tj * 128;
    const bool diag = (ti == tj);

    uint32_t sb = smem_u32(smem);
    int* sLI = (int*)(smem + SM_LAB);
    int* sLJ = sLI + 128;
    if (t < 128) sLI[t] = lab[i0 + t];
    else         sLJ[t - 128] = lab[j0 + t - 128];

    float acc[2][8][4];
#pragma unroll
    for (int mi = 0; mi < 2; mi++)
#pragma unroll
        for (int ni = 0; ni < 8; ni++)
#pragma unroll
            for (int r = 0; r < 4; r++) acc[mi][ni][r] = 0.f;

    const __nv_bfloat16* srcs[4] = { g_hi + (size_t)i0 * DK, g_lo + (size_t)i0 * DK,
                                     g_hi + (size_t)j0 * DK, g_lo + (size_t)j0 * DK };

    auto load_chunk = [&](int s, int kc) {
#pragma unroll
        for (int tile = 0; tile < 4; tile++) {
            uint32_t so = sb + (s * 4 + tile) * TILE_B;
#pragma unroll
            for (int i = 0; i < 2; i++) {
                int v = t + i * 256;        // 512 uint4 per tile
                int row = v >> 2, q = v & 3;
                cp16(so + row * (TSTR * 2) + q * 16,
                     srcs[tile] + (size_t)row * DK + kc * 32 + q * 8);
            }
        }
    };

    load_chunk(0, 0); cp_commit();

#pragma unroll 1
    for (int kc = 0; kc < 16; kc++) {
        int s = kc & 1;
        if (kc < 15) { load_chunk(s ^ 1, kc + 1); cp_commit(); cp_wait<1>(); }
        else         { cp_wait<0>(); }
        __syncthreads();

        const uint32_t aHi = sb + (s * 4 + 0) * TILE_B;
        const uint32_t aLo = sb + (s * 4 + 1) * TILE_B;
        const uint32_t bHi = sb + (s * 4 + 2) * TILE_B;
        const uint32_t bLo = sb + (s * 4 + 3) * TILE_B;

#pragma unroll
        for (int ks = 0; ks < 2; ks++) {
            const uint32_t a_off =
                (warp_m * 32 + (lid & 15)) * (TSTR * 2) + (ks * 16 + (lid >> 4) * 8) * 2;
            const uint32_t b_off =
                (warp_n * 64 + (lid & 7) + ((lid & 16) ? 8 : 0)) * (TSTR * 2) +
                (ks * 16 + ((lid >> 3) & 1) * 8) * 2;

            uint32_t a[2][4], bb[8][2];
            // pass 1: hi * hi
            ldsm4(a[0][0], a[0][1], a[0][2], a[0][3], aHi + a_off);
            ldsm4(a[1][0], a[1][1], a[1][2], a[1][3], aHi + a_off + 16 * (TSTR * 2));
#pragma unroll
            for (int np = 0; np < 4; np++)
                ldsm4(bb[2 * np][0], bb[2 * np][1], bb[2 * np + 1][0], bb[2 * np + 1][1],
                      bHi + b_off + np * 16 * (TSTR * 2));
#pragma unroll
            for (int mi = 0; mi < 2; mi++)
#pragma unroll
                for (int ni = 0; ni < 8; ni++) mma16816(acc[mi][ni], a[mi], bb[ni]);

            // pass 2: lo * hi (reuse b)
            ldsm4(a[0][0], a[0][1], a[0][2], a[0][3], aLo + a_off);
            ldsm4(a[1][0], a[1][1], a[1][2], a[1][3], aLo + a_off + 16 * (TSTR * 2));
#pragma unroll
            for (int mi = 0; mi < 2; mi++)
#pragma unroll
                for (int ni = 0; ni < 8; ni++) mma16816(acc[mi][ni], a[mi], bb[ni]);

            // pass 3: hi * lo
            ldsm4(a[0][0], a[0][1], a[0][2], a[0][3], aHi + a_off);
            ldsm4(a[1][0], a[1][1], a[1][2], a[1][3], aHi + a_off + 16 * (TSTR * 2));
#pragma unroll
            for (int np = 0; np < 4; np++)
                ldsm4(bb[2 * np][0], bb[2 * np][1], bb[2 * np + 1][0], bb[2 * np + 1][1],
                      bLo + b_off + np * 16 * (TSTR * 2));
#pragma unroll
            for (int mi = 0; mi < 2; mi++)
#pragma unroll
                for (int ni = 0; ni < 8; ni++) mma16816(acc[mi][ni], a[mi], bb[ni]);
        }
        __syncthreads();
    }

    // ---------------- fused epilogue ----------------
    const int r_l4 = lid >> 2, c_l4 = lid & 3;
    float rowacc[2][2] = {{0.f, 0.f}, {0.f, 0.f}};
    float colacc[8][2];
#pragma unroll
    for (int ni = 0; ni < 8; ni++) { colacc[ni][0] = 0.f; colacc[ni][1] = 0.f; }

#pragma unroll
    for (int mi = 0; mi < 2; mi++)
#pragma unroll
        for (int ni = 0; ni < 8; ni++)
#pragma unroll
            for (int r = 0; r < 4; r++) {
                int irow = warp_m * 32 + mi * 16 + (r >> 1) * 8 + r_l4;
                int jcol = warp_n * 64 + ni * 8 + c_l4 * 2 + (r & 1);
                int gi = i0 + irow, gj = j0 + jcol;
                float L = acc[mi][ni][r] * INV_T;
                if (sLI[irow] != sLJ[jcol]) {
                    float e = __expf(L - INV_T);
                    rowacc[mi][r >> 1] += e;
                    if (!diag) colacc[ni][r & 1] += e;
                } else if (gi != gj) {
                    int p = atomicAdd(&g_cnt[gi], 1);
                    if (p < NCAP) g_scr[gi * NCAP + p] = L;
                    if (!diag) {
                        int q = atomicAdd(&g_cnt[gj], 1);
                        if (q < NCAP) g_scr[gj * NCAP + q] = L;
                    }
                }
            }

#pragma unroll
    for (int mi = 0; mi < 2; mi++)
#pragma unroll
        for (int rp = 0; rp < 2; rp++) {
            float v = rowacc[mi][rp];
            v += __shfl_xor_sync(0xffffffffu, v, 1);
            v += __shfl_xor_sync(0xffffffffu, v, 2);
            if (c_l4 == 0)
                atomicAdd(&g_S[i0 + warp_m * 32 + mi * 16 + rp * 8 + r_l4], v);
        }
    if (!diag) {
#pragma unroll
        for (int ni = 0; ni < 8; ni++)
#pragma unroll
            for (int c = 0; c < 2; c++) {
                float v = colacc[ni][c];
                v += __shfl_xor_sync(0xffffffffu, v, 4);
                v += __shfl_xor_sync(0xffffffffu, v, 8);
                v += __shfl_xor_sync(0xffffffffu, v, 16);
                if (r_l4 == 0)
                    atomicAdd(&g_S[j0 + warp_n * 64 + ni * 8 + c_l4 * 2 + c], v);
            }
    }
}

__global__ void row_loss_kernel() {
    int i = blockIdx.x * blockDim.x + threadIdx.x;
    if (i >= NB) return;
    int c = g_cnt[i];
    float out = 0.f;
    if (c > 0) {
        float base = logf(g_S[i]) + INV_T;
        float s = 0.f;
        int cap = c < NCAP ? c : NCAP;
        for (int p = 0; p < cap; p++) {
            float L = g_scr[i * NCAP + p];
            s += log1pf(__expf(base - L));
        }
        out = s / (float)c;
    }
    g_rowloss[i] = out;
}

__global__ void reduce_kernel(float* __restrict__ out) {
    __shared__ float sm[256];
    float s = 0.f;
    for (int i = threadIdx.x; i < NB; i += 256) s += g_rowloss[i];
    sm[threadIdx.x] = s;
    __syncthreads();
    for (int o = 128; o > 0; o >>= 1) {
        if (threadIdx.x < o) sm[threadIdx.x] += sm[threadIdx.x + o];
        __syncthreads();
    }
    if (threadIdx.x == 0) out[0] = sm[0] * (1.0f / (float)NB);
}

extern "C" void kernel_launch(void* const* d_in, const int* in_sizes, int n_in,
                              void* d_out, int out_size) {
    const float* E   = (const float*)d_in[0];
    const int*   lab = (const int*)d_in[1];
    float*       out = (float*)d_out;

    static bool attr_set = false;
    if (!attr_set) {
        cudaFuncSetAttribute(gemm_mma, cudaFuncAttributeMaxDynamicSharedMemorySize, SM_TOTAL);
        attr_set = true;
    }

    init_kernel<<<NB / 256, 256>>>();
    convert_kernel<<<(NB * DK) / 256, 256>>>(E);
    gemm_mma<<<2080, 256, SM_TOTAL>>>(lab);   // 64*65/2 upper-triangle tiles
    row_loss_kernel<<<NB / 256, 256>>>();
    reduce_kernel<<<1, 256>>>(out);
}

// round 5
// speedup vs baseline: 6.1720x; 1.6747x over previous
#include <cuda_runtime.h>
#include <cuda_bf16.h>
#include <cstdint>
#include <math.h>

#define NB   8192
#define DK   512
#define NCAP 256
#define INV_T 14.285714285714285f

// ---------------- device scratch ----------------
__device__ float g_S[NB];
__device__ int   g_cnt[NB];
__device__ float g_scr[NB * NCAP];
__device__ float g_rowloss[NB];
__device__ __nv_bfloat16 g_hi[NB * DK];

// ---------------- tile geometry (BK=64) ----------------
#define TSTR   72                     // halves per smem row (144B: 4r%32 distinct banks)
#define TILE_B (128 * TSTR * 2)       // 18432 bytes per 128x64 bf16 tile
#define SM_LAB (4 * TILE_B)           // 2 stages x 2 tiles
#define SM_TOTAL (SM_LAB + 1024)

// ---------------- helpers ----------------
__device__ __forceinline__ uint32_t smem_u32(const void* p) {
    uint32_t a;
    asm("{ .reg .u64 t; cvta.to.shared.u64 t, %1; cvt.u32.u64 %0, t; }" : "=r"(a) : "l"(p));
    return a;
}
__device__ __forceinline__ void cp16(uint32_t dst, const void* src) {
    asm volatile("cp.async.cg.shared.global [%0], [%1], 16;" :: "r"(dst), "l"(src));
}
__device__ __forceinline__ void cp_commit() { asm volatile("cp.async.commit_group;"); }
template<int N> __device__ __forceinline__ void cp_wait() {
    asm volatile("cp.async.wait_group %0;" :: "n"(N));
}
__device__ __forceinline__ void ldsm4(uint32_t& r0, uint32_t& r1, uint32_t& r2, uint32_t& r3,
                                      uint32_t addr) {
    asm volatile("ldmatrix.sync.aligned.m8n8.x4.shared.b16 {%0,%1,%2,%3}, [%4];"
                 : "=r"(r0), "=r"(r1), "=r"(r2), "=r"(r3) : "r"(addr));
}
__device__ __forceinline__ void mma16816(float* c, const uint32_t* a, const uint32_t* b) {
    asm volatile("mma.sync.aligned.m16n8k16.row.col.f32.bf16.bf16.f32 "
                 "{%0,%1,%2,%3},{%4,%5,%6,%7},{%8,%9},{%0,%1,%2,%3};"
                 : "+f"(c[0]), "+f"(c[1]), "+f"(c[2]), "+f"(c[3])
                 : "r"(a[0]), "r"(a[1]), "r"(a[2]), "r"(a[3]), "r"(b[0]), "r"(b[1]));
}

// convert fp32 -> bf16, and zero the accumulators in the same launch
__global__ void convert_kernel(const float* __restrict__ E) {
    int i = blockIdx.x * blockDim.x + threadIdx.x;
    if (i < NB) { g_S[i] = 0.f; g_cnt[i] = 0; }
    g_hi[i] = __float2bfloat16(E[i]);
}

extern __shared__ char smem[];

// Upper-triangle tiled symmetric GEMM (E E^T) on HMMA bf16 (single pass), fused epilogue.
__global__ void __launch_bounds__(256, 2) gemm_mma(const int* __restrict__ lab) {
    const int t   = threadIdx.x;
    const int lid = t & 31;
    const int wid = t >> 5;
    const int warp_m = wid & 3;     // 4 warps down  (32 rows each)
    const int warp_n = wid >> 2;    // 2 warps across (64 cols each)

    // decode upper-triangle tile (ti <= tj), cum(t) = t*(129-t)/2
    int b  = blockIdx.x;
    int ti = (int)((129.0 - sqrt(129.0 * 129.0 - 8.0 * (double)b)) * 0.5);
    while (ti * (129 - ti) / 2 > b) ti--;
    while ((ti + 1) * (128 - ti) / 2 <= b) ti++;
    const int tj = ti + (b - ti * (129 - ti) / 2);
    const int i0 = ti * 128, j0 = tj * 128;
    const bool diag = (ti == tj);

    uint32_t sb = smem_u32(smem);
    int* sLI = (int*)(smem + SM_LAB);
    int* sLJ = sLI + 128;
    if (t < 128) sLI[t] = lab[i0 + t];
    else         sLJ[t - 128] = lab[j0 + t - 128];

    float acc[2][8][4];
#pragma unroll
    for (int mi = 0; mi < 2; mi++)
#pragma unroll
        for (int ni = 0; ni < 8; ni++)
#pragma unroll
            for (int r = 0; r < 4; r++) acc[mi][ni][r] = 0.f;

    const __nv_bfloat16* srcA = g_hi + (size_t)i0 * DK;
    const __nv_bfloat16* srcB = g_hi + (size_t)j0 * DK;

    // Load one 128x64 bf16 tile pair into stage s for k-chunk kc
    auto load_chunk = [&](int s, int kc) {
#pragma unroll
        for (int tile = 0; tile < 2; tile++) {
            const __nv_bfloat16* base = tile ? srcB : srcA;
            uint32_t so = sb + (s * 2 + tile) * TILE_B;
#pragma unroll
            for (int i = 0; i < 4; i++) {
                int v = t + i * 256;            // 1024 x 16B chunks per tile
                int row = v >> 3, q = v & 7;
                cp16(so + row * (TSTR * 2) + q * 16,
                     base + (size_t)row * DK + kc * 64 + q * 8);
            }
        }
    };

    load_chunk(0, 0); cp_commit();

#pragma unroll 1
    for (int kc = 0; kc < 8; kc++) {
        int s = kc & 1;
        if (kc < 7) { load_chunk(s ^ 1, kc + 1); cp_commit(); cp_wait<1>(); }
        else        { cp_wait<0>(); }
        __syncthreads();

        const uint32_t aT = sb + (s * 2 + 0) * TILE_B;
        const uint32_t bT = sb + (s * 2 + 1) * TILE_B;

#pragma unroll
        for (int ks = 0; ks < 4; ks++) {
            const uint32_t a_off =
                (warp_m * 32 + (lid & 15)) * (TSTR * 2) + (ks * 16 + (lid >> 4) * 8) * 2;
            const uint32_t b_off =
                (warp_n * 64 + (lid & 7) + ((lid & 16) ? 8 : 0)) * (TSTR * 2) +
                (ks * 16 + ((lid >> 3) & 1) * 8) * 2;

            uint32_t a[2][4], bb[8][2];
            ldsm4(a[0][0], a[0][1], a[0][2], a[0][3], aT + a_off);
            ldsm4(a[1][0], a[1][1], a[1][2], a[1][3], aT + a_off + 16 * (TSTR * 2));
#pragma unroll
            for (int np = 0; np < 4; np++)
                ldsm4(bb[2 * np][0], bb[2 * np][1], bb[2 * np + 1][0], bb[2 * np + 1][1],
                      bT + b_off + np * 16 * (TSTR * 2));
#pragma unroll
            for (int mi = 0; mi < 2; mi++)
#pragma unroll
                for (int ni = 0; ni < 8; ni++) mma16816(acc[mi][ni], a[mi], bb[ni]);
        }
        __syncthreads();
    }

    // ---------------- fused epilogue ----------------
    const int r_l4 = lid >> 2, c_l4 = lid & 3;
    float rowacc[2][2] = {{0.f, 0.f}, {0.f, 0.f}};
    float colacc[8][2];
#pragma unroll
    for (int ni = 0; ni < 8; ni++) { colacc[ni][0] = 0.f; colacc[ni][1] = 0.f; }

#pragma unroll
    for (int mi = 0; mi < 2; mi++)
#pragma unroll
        for (int ni = 0; ni < 8; ni++)
#pragma unroll
            for (int r = 0; r < 4; r++) {
                int irow = warp_m * 32 + mi * 16 + (r >> 1) * 8 + r_l4;
                int jcol = warp_n * 64 + ni * 8 + c_l4 * 2 + (r & 1);
                int gi = i0 + irow, gj = j0 + jcol;
                float L = acc[mi][ni][r] * INV_T;
                if (sLI[irow] != sLJ[jcol]) {
                    float e = __expf(L - INV_T);
                    rowacc[mi][r >> 1] += e;
                    if (!diag) colacc[ni][r & 1] += e;
                } else if (gi != gj) {
                    int p = atomicAdd(&g_cnt[gi], 1);
                    if (p < NCAP) g_scr[gi * NCAP + p] = L;
                    if (!diag) {
                        int q = atomicAdd(&g_cnt[gj], 1);
                        if (q < NCAP) g_scr[gj * NCAP + q] = L;
                    }
                }
            }

#pragma unroll
    for (int mi = 0; mi < 2; mi++)
#pragma unroll
        for (int rp = 0; rp < 2; rp++) {
            float v = rowacc[mi][rp];
            v += __shfl_xor_sync(0xffffffffu, v, 1);
            v += __shfl_xor_sync(0xffffffffu, v, 2);
            if (c_l4 == 0)
                atomicAdd(&g_S[i0 + warp_m * 32 + mi * 16 + rp * 8 + r_l4], v);
        }
    if (!diag) {
#pragma unroll
        for (int ni = 0; ni < 8; ni++)
#pragma unroll
            for (int c = 0; c < 2; c++) {
                float v = colacc[ni][c];
                v += __shfl_xor_sync(0xffffffffu, v, 4);
                v += __shfl_xor_sync(0xffffffffu, v, 8);
                v += __shfl_xor_sync(0xffffffffu, v, 16);
                if (r_l4 == 0)
                    atomicAdd(&g_S[j0 + warp_n * 64 + ni * 8 + c_l4 * 2 + c], v);
            }
    }
}

// Pass 2: warp per row for parallelism over stored positives
__global__ void row_loss_kernel() {
    int wid_g = (blockIdx.x * blockDim.x + threadIdx.x) >> 5;
    int lid   = threadIdx.x & 31;
    if (wid_g >= NB) return;
    int i = wid_g;
    int c = g_cnt[i];
    float s = 0.f;
    if (c > 0) {
        float base = logf(g_S[i]) + INV_T;
        int cap = c < NCAP ? c : NCAP;
        for (int p = lid; p < cap; p += 32) {
            float L = g_scr[i * NCAP + p];
            s += log1pf(__expf(base - L));
        }
        s += __shfl_xor_sync(0xffffffffu, s, 16);
        s += __shfl_xor_sync(0xffffffffu, s, 8);
        s += __shfl_xor_sync(0xffffffffu, s, 4);
        s += __shfl_xor_sync(0xffffffffu, s, 2);
        s += __shfl_xor_sync(0xffffffffu, s, 1);
        s /= (float)c;
    }
    if (lid == 0) g_rowloss[i] = s;
}

__global__ void reduce_kernel(float* __restrict__ out) {
    __shared__ float sm[256];
    float s = 0.f;
    for (int i = threadIdx.x; i < NB; i += 256) s += g_rowloss[i];
    sm[threadIdx.x] = s;
    __syncthreads();
    for (int o = 128; o > 0; o >>= 1) {
        if (threadIdx.x < o) sm[threadIdx.x] += sm[threadIdx.x + o];
        __syncthreads();
    }
    if (threadIdx.x == 0) out[0] = sm[0] * (1.0f / (float)NB);
}

extern "C" void kernel_launch(void* const* d_in, const int* in_sizes, int n_in,
                              void* d_out, int out_size) {
    const float* E   = (const float*)d_in[0];
    const int*   lab = (const int*)d_in[1];
    float*       out = (float*)d_out;

    static bool attr_set = false;
    if (!attr_set) {
        cudaFuncSetAttribute(gemm_mma, cudaFuncAttributeMaxDynamicSharedMemorySize, SM_TOTAL);
        attr_set = true;
    }

    convert_kernel<<<(NB * DK) / 256, 256>>>(E);
    gemm_mma<<<2080, 256, SM_TOTAL>>>(lab);        // 64*65/2 upper-triangle tiles
    row_loss_kernel<<<NB / 8, 256>>>();            // warp per row
    reduce_kernel<<<1, 256>>>(out);
}